// round 15
// baseline (speedup 1.0000x reference)
#include <cuda_runtime.h>
#include <cuda_fp16.h>

// ---------------- problem dims ----------------
#define Bc   1024
#define Tc   100
#define Dc   256
#define Hc   256
#define Gc   1024
#define Mc   64
#define GMc  256

typedef unsigned long long ull;
typedef unsigned int u32;

// ---------------- device scratch ----------------
__device__ float g_xg  [(size_t)Bc * Tc * Gc / 2];  // fp16 xg (enc1)
__device__ float g_mid [(size_t)Bc * Tc * Hc];      // fp16 h_enc0 / fp16 xg_dec1
__device__ float g_bufA[(size_t)Bc * Tc * Mc];      // fp16 h0 / d0
__device__ float g_bufB[(size_t)Bc * Tc * Mc * 2];  // fp16 x_h, later fp16 d1
__device__ float g_z   [Bc * Hc];                   // fp16 z
__device__ float g_xgd0[Bc * GMc];                  // fp32
__device__ uint4 g_wh0 [32768];                     // enc0 Whh fp16 B-fragments (512 KB)
__device__ uint4 g_wh1 [32768];
__device__ uint2 g_wpf0[16384];                     // enc0 Wih fp16 B-fragments (K=64)
__device__ float  g_bp0 [Gc];
__device__ __half g_wp1h[Gc * Hc];
__device__ float  g_bp1 [Gc];
__device__ __half g_wih [128 * Dc];
__device__ __half g_wd0h[GMc * Hc];
__device__ __half g_wd1h[GMc * Mc];
__device__ __half g_woh [Dc * Mc];
__device__ float g_w4d0[(Mc * Mc + 1024) * 4];
__device__ float g_w4d1[(Mc * Mc + 1024) * 4];

// ---------------- helpers ----------------
__device__ __forceinline__ ull pack2f(float x, float y) {
    ull r; asm("mov.b64 %0, {%1, %2};" : "=l"(r) : "f"(x), "f"(y)); return r;
}
__device__ __forceinline__ float2 unpack2f(ull v) {
    float2 r; asm("mov.b64 {%0, %1}, %2;" : "=f"(r.x), "=f"(r.y) : "l"(v)); return r;
}
__device__ __forceinline__ ull fma2f(ull a, ull b, ull c) {
    ull d; asm("fma.rn.f32x2 %0, %1, %2, %3;" : "=l"(d) : "l"(a), "l"(b), "l"(c)); return d;
}
__device__ __forceinline__ float tanha(float x) {
    float r; asm("tanh.approx.f32 %0, %1;" : "=f"(r) : "f"(x)); return r;
}
__device__ __forceinline__ float sigt(float x) {
    return fmaf(tanha(0.5f * x), 0.5f, 0.5f);
}
__device__ __forceinline__ void mma_f16(float4& d, u32 a0, u32 a1, u32 a2, u32 a3,
                                        u32 b0, u32 b1) {
    asm("mma.sync.aligned.m16n8k16.row.col.f32.f16.f16.f32 "
        "{%0,%1,%2,%3}, {%4,%5,%6,%7}, {%8,%9}, {%0,%1,%2,%3};"
        : "+f"(d.x), "+f"(d.y), "+f"(d.z), "+f"(d.w)
        : "r"(a0), "r"(a1), "r"(a2), "r"(a3), "r"(b0), "r"(b1));
}
__device__ __forceinline__ u32 packh2(float a, float b) {
    __half2 h = __floats2half2_rn(a, b);
    return *(u32*)&h;
}
__device__ __forceinline__ float2 unpackh2(u32 v) {
    return __half22float2(*(__half2*)&v);
}
__device__ __forceinline__ uint4 ldsm4(u32 addr) {
    uint4 r;
    asm volatile("ldmatrix.sync.aligned.m8n8.x4.shared.b16 {%0,%1,%2,%3}, [%4];"
                 : "=r"(r.x), "=r"(r.y), "=r"(r.z), "=r"(r.w) : "r"(addr));
    return r;
}

// ===== cluster-4 gate permutation =====
// n' = rank*256 + w*16 + nt*8 + (jl*2 + glo);  gate g = 2*nt + glo
// orig = g*256 + rank*64 + w*4 + jl
__device__ __forceinline__ int perm4_orig(int np) {
    int rank = np >> 8, w = (np >> 4) & 15, rem = np & 15;
    int nt = rem >> 3, cc = rem & 7;
    int jl = cc >> 1, glo = cc & 1, g = 2 * nt + glo;
    return g * 256 + rank * 64 + w * 4 + jl;
}

// ---------------- enc0 prep: Whh frags + Wih frags + bias (cluster-4) -------------
__global__ void prep_enc0(const float* __restrict__ Wh, const float* __restrict__ Wi,
                          const float* __restrict__ bi, const float* __restrict__ bh,
                          uint2* __restrict__ wh, uint2* __restrict__ wpf,
                          float* __restrict__ bp) {
    int bx = blockIdx.x;
    if (bx < 256) {
        int t2 = bx * 256 + threadIdx.x;
        int lane = t2 & 31, nt = (t2 >> 5) & 1, w = (t2 >> 6) & 15;
        int rank = (t2 >> 10) & 3, c = t2 >> 12;
        int gid = lane >> 2, tt = lane & 3;
        int np = rank * 256 + w * 16 + nt * 8 + gid;
        int n = perm4_orig(np);
        int k0 = 16 * c + 2 * tt;
        uint2 v;
        v.x = packh2(Wh[(size_t)n * Hc + k0],     Wh[(size_t)n * Hc + k0 + 1]);
        v.y = packh2(Wh[(size_t)n * Hc + k0 + 8], Wh[(size_t)n * Hc + k0 + 9]);
        wh[t2] = v;
    } else if (bx < 320) {
        int t2 = (bx - 256) * 256 + threadIdx.x;   // c 0..3
        int lane = t2 & 31, nt = (t2 >> 5) & 1, w = (t2 >> 6) & 15;
        int rank = (t2 >> 10) & 3, c = t2 >> 12;
        int gid = lane >> 2, tt = lane & 3;
        int np = rank * 256 + w * 16 + nt * 8 + gid;
        int n = perm4_orig(np);
        int k0 = 16 * c + 2 * tt;
        uint2 v;
        v.x = packh2(Wi[(size_t)n * 64 + k0],     Wi[(size_t)n * 64 + k0 + 1]);
        v.y = packh2(Wi[(size_t)n * 64 + k0 + 8], Wi[(size_t)n * 64 + k0 + 9]);
        wpf[t2] = v;
    } else {
        for (int i = threadIdx.x; i < Gc; i += 256) {
            int orig = perm4_orig(i);
            bp[i] = bi[orig] + bh[orig];
        }
    }
}

// ---------------- enc1 prep: Whh frags + permuted Wih(fp16)/bias ----------------
__global__ void prep_enc1(const float* __restrict__ Wh, const float* __restrict__ Wi,
                          const float* __restrict__ bi, const float* __restrict__ bh,
                          uint2* __restrict__ wh, __half* __restrict__ Wp,
                          float* __restrict__ bp) {
    int bx = blockIdx.x;
    if (bx < 256) {
        int t2 = bx * 256 + threadIdx.x;
        int lane = t2 & 31, nt = (t2 >> 5) & 1, w = (t2 >> 6) & 15;
        int rank = (t2 >> 10) & 3, c = t2 >> 12;
        int gid = lane >> 2, tt = lane & 3;
        int np = rank * 256 + w * 16 + nt * 8 + gid;
        int n = perm4_orig(np);
        int k0 = 16 * c + 2 * tt;
        uint2 v;
        v.x = packh2(Wh[(size_t)n * Hc + k0],     Wh[(size_t)n * Hc + k0 + 1]);
        v.y = packh2(Wh[(size_t)n * Hc + k0 + 8], Wh[(size_t)n * Hc + k0 + 9]);
        wh[t2] = v;
    } else {
        int np = bx - 256;                  // 0..1023
        int orig = perm4_orig(np);
        for (int k = threadIdx.x; k < Hc; k += blockDim.x)
            Wp[(size_t)np * Hc + k] = __float2half(Wi[(size_t)orig * Hc + k]);
        if (threadIdx.x == 0) bp[np] = bi[orig] + bh[orig];
    }
}

// ---------------- merged misc converts ----------------
__global__ void prep_misc(const float* __restrict__ Wi, const float* __restrict__ d0,
                          const float* __restrict__ d1, const float* __restrict__ ow,
                          __half* __restrict__ wih, __half* __restrict__ wd0h,
                          __half* __restrict__ wd1h, __half* __restrict__ woh) {
    int bx = blockIdx.x;
    if (bx < 128) {
        int i = bx * 256 + threadIdx.x;
        wih[i] = ((i >> 8) < 64) ? __float2half(Wi[i]) : __half(0.f);
    } else if (bx < 384) {
        int i = (bx - 128) * 256 + threadIdx.x;
        wd0h[i] = __float2half(d0[i]);
    } else if (bx < 448) {
        int i = (bx - 384) * 256 + threadIdx.x;
        wd1h[i] = __float2half(d1[i]);
    } else {
        int i = (bx - 448) * 256 + threadIdx.x;
        woh[i] = __float2half(ow[i]);
    }
}

__global__ void cvt16v(const float4* __restrict__ src, uint2* __restrict__ dst, int n4) {
    int i = blockIdx.x * 256 + threadIdx.x;
    if (i < n4) {
        float4 v = src[i];
        dst[i] = make_uint2(packh2(v.x, v.y), packh2(v.z, v.w));
    }
}

// ---------------- dec weight prep ----------------
__global__ void prep_w4(const float* __restrict__ src, float* __restrict__ dst, int H) {
    __shared__ float tile[32][33];
    int g = blockIdx.z;
    int k0 = blockIdx.x * 32, j0 = blockIdx.y * 32;
    int x = threadIdx.x, y = threadIdx.y;
#pragma unroll
    for (int i = 0; i < 32; i += 8)
        tile[y + i][x] = src[(size_t)(g * H + j0 + y + i) * H + k0 + x];
    __syncthreads();
#pragma unroll
    for (int i = 0; i < 32; i += 8)
        dst[((size_t)(k0 + y + i) * H + (j0 + x)) * 4 + g] = tile[x][y + i];
}

// ---------------- fp16 GEMM: cp.async(3-stage) + ldmatrix + m16n8k16 ----------------
template <bool HASB2, bool HOUT, bool RELU, bool NGUARD>
__global__ void __launch_bounds__(256, 2) gemm_h(
    const __half* __restrict__ A, const __half* __restrict__ W,
    const float* __restrict__ b1, const float* __restrict__ b2,
    void* __restrict__ Cv, int Mdim, int Ndim, int Kdim) {
    __shared__ __align__(16) char smtile[3][16384];

    const int tid = threadIdx.x, lane = tid & 31, wid = tid >> 5;
    const int wm = wid & 3, wn = wid >> 2;
    const int gid = lane >> 2, tig = lane & 3;
    const size_t bm = (size_t)blockIdx.x * 128;
    const size_t bn = (size_t)blockIdx.y * 128;

    u32 smb;
    asm("{ .reg .u64 t; cvta.to.shared.u64 t, %1; cvt.u32.u64 %0, t; }"
        : "=r"(smb) : "l"((void*)smtile));

    u32 dA[2], dB[2];
    const __half* sA[2];
    const __half* sB[2];
#pragma unroll
    for (int i = 0; i < 2; i++) {
        int fidx = tid * 2 + i;
        int row = fidx >> 2, kc = fidx & 3;
        u32 off = (u32)(row * 64 + ((kc ^ (row & 3)) << 4));
        dA[i] = smb + off;
        sA[i] = A + (bm + row) * (size_t)Kdim + kc * 8;
        dB[i] = smb + 8192 + off;
        sB[i] = W + (bn + row) * (size_t)Kdim + kc * 8;
    }

    u32 oA[2][2], oB[2][4];
#pragma unroll
    for (int mt = 0; mt < 2; mt++) {
        int rA = wm * 32 + mt * 16 + (lane & 7) + ((lane >> 3) & 1) * 8;
#pragma unroll
        for (int s = 0; s < 2; s++) {
            int ch = s * 2 + (lane >> 4);
            oA[s][mt] = smb + rA * 64 + ((ch ^ (rA & 3)) << 4);
        }
    }
#pragma unroll
    for (int np = 0; np < 4; np++) {
        int rB = wn * 64 + np * 16 + (lane & 7) + ((lane >> 4) & 1) * 8;
#pragma unroll
        for (int s = 0; s < 2; s++) {
            int ch = s * 2 + ((lane >> 3) & 1);
            oB[s][np] = smb + 8192 + rB * 64 + ((ch ^ (rB & 3)) << 4);
        }
    }

    float4 acc[2][8];
#pragma unroll
    for (int mt = 0; mt < 2; mt++)
#pragma unroll
        for (int nt = 0; nt < 8; nt++) acc[mt][nt] = make_float4(0.f, 0.f, 0.f, 0.f);

#define GH_FILL(BUF, K0)                                                       \
    _Pragma("unroll")                                                          \
    for (int i_ = 0; i_ < 2; i_++) {                                           \
        asm volatile("cp.async.cg.shared.global [%0], [%1], 16;"               \
                     :: "r"(dA[i_] + (BUF) * 16384u), "l"(sA[i_] + (K0)) : "memory"); \
        asm volatile("cp.async.cg.shared.global [%0], [%1], 16;"               \
                     :: "r"(dB[i_] + (BUF) * 16384u), "l"(sB[i_] + (K0)) : "memory"); \
    }                                                                          \
    asm volatile("cp.async.commit_group;" ::: "memory");

#define GH_COMP(BUF)                                                           \
    _Pragma("unroll")                                                          \
    for (int s_ = 0; s_ < 2; s_++) {                                           \
        uint4 af0 = ldsm4(oA[s_][0] + (BUF) * 16384u);                         \
        uint4 af1 = ldsm4(oA[s_][1] + (BUF) * 16384u);                         \
        _Pragma("unroll")                                                      \
        for (int np_ = 0; np_ < 4; np_++) {                                    \
            uint4 bf = ldsm4(oB[s_][np_] + (BUF) * 16384u);                    \
            mma_f16(acc[0][2 * np_],     af0.x, af0.y, af0.z, af0.w, bf.x, bf.y); \
            mma_f16(acc[0][2 * np_ + 1], af0.x, af0.y, af0.z, af0.w, bf.z, bf.w); \
            mma_f16(acc[1][2 * np_],     af1.x, af1.y, af1.z, af1.w, bf.x, bf.y); \
            mma_f16(acc[1][2 * np_ + 1], af1.x, af1.y, af1.z, af1.w, bf.z, bf.w); \
        }                                                                      \
    }

    const int nb = Kdim >> 5;
    GH_FILL(0, 0);
    GH_FILL(1, 32);
#pragma unroll 1
    for (int it = 0; it < nb - 1; it++) {
        asm volatile("cp.async.wait_group 1;" ::: "memory");
        __syncthreads();
        if (it + 2 < nb) { int b2_ = (it + 2) % 3; GH_FILL(b2_, (it + 2) * 32); }
        GH_COMP(it % 3);
        __syncthreads();
    }
    asm volatile("cp.async.wait_group 0;" ::: "memory");
    __syncthreads();
    GH_COMP((nb - 1) % 3);

#pragma unroll
    for (int mt = 0; mt < 2; mt++) {
        int row0 = (int)bm + wm * 32 + mt * 16 + gid;
#pragma unroll
        for (int nt = 0; nt < 8; nt++) {
            int col = (int)bn + wn * 64 + nt * 8 + 2 * tig;
            if (NGUARD && col >= Ndim) continue;
            float bb0 = b1[col], bb1 = b1[col + 1];
            if (HASB2) { bb0 += b2[col]; bb1 += b2[col + 1]; }
            float v0 = acc[mt][nt].x + bb0, v1 = acc[mt][nt].y + bb1;
            float v2 = acc[mt][nt].z + bb0, v3 = acc[mt][nt].w + bb1;
            if (RELU) {
                v0 = fmaxf(v0, 0.f); v1 = fmaxf(v1, 0.f);
                v2 = fmaxf(v2, 0.f); v3 = fmaxf(v3, 0.f);
            }
            if (HOUT) {
                u32* Ch = (u32*)Cv;
                Ch[((size_t)row0 * Ndim + col) >> 1]       = packh2(v0, v1);
                Ch[((size_t)(row0 + 8) * Ndim + col) >> 1] = packh2(v2, v3);
            } else {
                float* C = (float*)Cv;
                *(float2*)&C[(size_t)row0 * Ndim + col]       = make_float2(v0, v1);
                *(float2*)&C[(size_t)(row0 + 8) * Ndim + col] = make_float2(v2, v3);
            }
        }
    }
}

// ================= cluster-4 encoder LSTM =================
// 128 CTAs = 32 clusters x 4. CTA: 32 rows x 256 gate cols, weights FULLY smem-resident.
#define H4_STRIDE 40
#define H4_BYTES  (128 * H4_STRIDE * 4)      // 20480
#define WHH_OFF   (2 * H4_BYTES)             // 40960
#define ENC4_SMEM (WHH_OFF + 131072)         // 172032
#define WIH_OFF   (WHH_OFF + 131072)         // 172032 (enc0)
#define H0T_OFF   (WIH_OFF + 32768)          // 204800
#define ENC0_SMEM (H0T_OFF + 2 * 4224)       // 213248

#define CP_WAIT0() asm volatile("cp.async.wait_group 0;" ::: "memory")
#define CL_ARRIVE() asm volatile("barrier.cluster.arrive.aligned;" ::: "memory")
#define CL_WAIT()   asm volatile("barrier.cluster.wait.aligned;" ::: "memory")

#define ENC4_PRELUDE                                                           \
    extern __shared__ __align__(16) char sm[];                                 \
    const int tid = threadIdx.x, lane = tid & 31, w = tid >> 5;                \
    const int gid = lane >> 2, tg = lane & 3;                                  \
    u32 rank;                                                                  \
    asm("mov.u32 %0, %%cluster_ctarank;" : "=r"(rank));                        \
    const int b0 = (blockIdx.x >> 2) * 32;                                     \
    u32 smb;                                                                   \
    asm("{ .reg .u64 t; cvta.to.shared.u64 t, %1; cvt.u32.u64 %0, t; }"        \
        : "=r"(smb) : "l"((void*)sm));                                         \
    u32 rb[3];                                                                 \
    _Pragma("unroll")                                                          \
    for (int p = 0; p < 3; p++) {                                              \
        u32 pr = (rank + 1 + p) & 3;                                           \
        asm("mapa.shared::cluster.u32 %0, %1, %2;" : "=r"(rb[p]) : "r"(smb), "r"(pr)); \
    }

// copy this CTA's slice of frag weights (16B per lane per chunk)
#define LOAD_FRAGS(dst_off, src, NCH)                                          \
    _Pragma("unroll")                                                          \
    for (int c = 0; c < (NCH); c++) {                                          \
        u32 dst_ = smb + (dst_off) + ((c * 16 + w) * 64 + lane * 2) * 8;       \
        const uint2* s_ = (src) + ((c * 4 + (int)rank) * 16 + w) * 64 + lane * 2; \
        asm volatile("cp.async.cg.shared.global [%0], [%1], 16;"               \
                     :: "r"(dst_), "l"(s_) : "memory");                        \
    }

#define CHUNK4(c)                                                              \
    {                                                                          \
        const uint2* bb = (const uint2*)(sm + WHH_OFF) + ((c) * 16 + w) * 64;  \
        uint2 b0t = bb[lane], b1t = bb[32 + lane];                             \
        _Pragma("unroll")                                                      \
        for (int mt = 0; mt < 2; mt++) {                                       \
            int r_ = mt * 16 + gid;                                            \
            u32 a0 = hc[(8 * (c) + tg) * H4_STRIDE + r_];                      \
            u32 a1 = hc[(8 * (c) + tg) * H4_STRIDE + r_ + 8];                  \
            u32 a2 = hc[(8 * (c) + 4 + tg) * H4_STRIDE + r_];                  \
            u32 a3 = hc[(8 * (c) + 4 + tg) * H4_STRIDE + r_ + 8];              \
            mma_f16(acc[mt][0], a0, a1, a2, a3, b0t.x, b0t.y);                 \
            mma_f16(acc[mt][1], a0, a1, a2, a3, b1t.x, b1t.y);                 \
        }                                                                      \
    }

// epilogue: per mt, IF/GO accumulators + addend float2s -> h, c-state
#define ENC4_EPI(ADD_IF0, ADD_IF1, ADD_GO0, ADD_GO1, MT)                       \
    {                                                                          \
        float4 IF = acc[MT][0], GO = acc[MT][1];                               \
        float Iv0 = IF.x + (ADD_IF0).x, Fv0 = IF.y + (ADD_IF0).y;              \
        float Gv0 = GO.x + (ADD_GO0).x, Ov0 = GO.y + (ADD_GO0).y;              \
        float Iv1 = IF.z + (ADD_IF1).x, Fv1 = IF.w + (ADD_IF1).y;              \
        float Gv1 = GO.z + (ADD_GO1).x, Ov1 = GO.w + (ADD_GO1).y;              \
        float cc0 = sigt(Fv0) * cst[2 * (MT)] + sigt(Iv0) * tanha(Gv0);        \
        cst[2 * (MT)] = cc0;                                                   \
        hv[2 * (MT)] = sigt(Ov0) * tanha(cc0);                                 \
        float cc1 = sigt(Fv1) * cst[2 * (MT) + 1] + sigt(Iv1) * tanha(Gv1);    \
        cst[2 * (MT) + 1] = cc1;                                               \
        hv[2 * (MT) + 1] = sigt(Ov1) * tanha(cc1);                             \
    }

// shfl-pack + store h (local + 3 remotes); even-tg threads store
#define ENC4_STORE_H()                                                         \
    u32 pu[4];                                                                 \
    {                                                                          \
        float ph0 = __shfl_xor_sync(0xffffffffu, hv[0], 1);                    \
        float ph1 = __shfl_xor_sync(0xffffffffu, hv[1], 1);                    \
        float ph2 = __shfl_xor_sync(0xffffffffu, hv[2], 1);                    \
        float ph3 = __shfl_xor_sync(0xffffffffu, hv[3], 1);                    \
        if ((tg & 1) == 0) {                                                   \
            pu[0] = packh2(hv[0], ph0);                                        \
            pu[1] = packh2(hv[1], ph1);                                        \
            pu[2] = packh2(hv[2], ph2);                                        \
            pu[3] = packh2(hv[3], ph3);                                        \
            const u32 hno = (u32)((cur ^ 1) * H4_BYTES);                       \
            _Pragma("unroll")                                                  \
            for (int r_ = 0; r_ < 4; r_++) {                                   \
                u32 off = hno + (u32)((k2 * H4_STRIDE + lr[r_]) * 4);          \
                *(u32*)(sm + off) = pu[r_];                                    \
                asm volatile("st.shared::cluster.u32 [%0], %1;" :: "r"(rb[0] + off), "r"(pu[r_])); \
                asm volatile("st.shared::cluster.u32 [%0], %1;" :: "r"(rb[1] + off), "r"(pu[r_])); \
                asm volatile("st.shared::cluster.u32 [%0], %1;" :: "r"(rb[2] + off), "r"(pu[r_])); \
            }                                                                  \
        }                                                                      \
    }

// ---------------- enc1: xg from gmem, Whh resident ----------------
__global__ void __launch_bounds__(512, 1) __cluster_dims__(4, 1, 1)
lstm_enc4(const uint2* __restrict__ wh, const __half* __restrict__ xgh,
          u32* __restrict__ z_last) {
    ENC4_PRELUDE

    LOAD_FRAGS(WHH_OFF, wh, 16);
    asm volatile("cp.async.commit_group;" ::: "memory");
    for (int i = tid; i < 2 * H4_BYTES / 4; i += 512) ((u32*)sm)[i] = 0;
    CP_WAIT0();
    CL_ARRIVE();

    float4 acc[2][2];
    float cst[4] = {0.f, 0.f, 0.f, 0.f};
    float hv[4];
    const int k2 = (int)rank * 32 + w * 2 + (tg >> 1);
    const int lr[4] = {gid, gid + 8, 16 + gid, 24 + gid};
    const int cbase = (int)rank * 256 + w * 16;
    int cur = 0;

#pragma unroll 1
    for (int t = 0; t < Tc; t++) {
        const u32* hc = (const u32*)(sm + cur * H4_BYTES);

        u32 xif[4], xgo[4];
#pragma unroll
        for (int r = 0; r < 4; r++) {
            const __half* xr = xgh + ((size_t)(b0 + lr[r]) * Tc + t) * Gc + cbase;
            xif[r] = *(const u32*)(xr + 2 * tg);
            xgo[r] = *(const u32*)(xr + 8 + 2 * tg);
        }
#pragma unroll
        for (int mt = 0; mt < 2; mt++) {
            acc[mt][0] = make_float4(0.f, 0.f, 0.f, 0.f);
            acc[mt][1] = make_float4(0.f, 0.f, 0.f, 0.f);
        }

        CL_WAIT();

#pragma unroll
        for (int c = 0; c < 16; c++) CHUNK4(c);

        {
            float2 if0 = unpackh2(xif[0]), if1 = unpackh2(xif[1]);
            float2 go0 = unpackh2(xgo[0]), go1 = unpackh2(xgo[1]);
            ENC4_EPI(if0, if1, go0, go1, 0)
            float2 if2 = unpackh2(xif[2]), if3 = unpackh2(xif[3]);
            float2 go2 = unpackh2(xgo[2]), go3 = unpackh2(xgo[3]);
            ENC4_EPI(if2, if3, go2, go3, 1)
        }
        ENC4_STORE_H()
        CL_ARRIVE();

        if (t == Tc - 1 && (tg & 1) == 0) {
#pragma unroll
            for (int r = 0; r < 4; r++)
                z_last[(size_t)(b0 + lr[r]) * (Hc / 2) + k2] = pu[r];
        }
        cur ^= 1;
    }
    CL_WAIT();
}

// ---------------- enc0: fused input projection, all weights resident -------------
__global__ void __launch_bounds__(512, 1) __cluster_dims__(4, 1, 1)
lstm_enc0f(const uint2* __restrict__ wh, const uint2* __restrict__ wpf,
           const __half* __restrict__ h0g, const float* __restrict__ bp,
           u32* __restrict__ h_all) {
    ENC4_PRELUDE

// FIXED: two 4-byte cp.async (dst row stride 132 B is only 4-aligned on odd rows)
#define ISSUE_H0(T)                                                            \
    {                                                                          \
        int row_ = tid >> 4, c16_ = tid & 15;                                  \
        u32 dst_ = smb + H0T_OFF + (((T) & 1) ? 4224u : 0u) + (u32)(row_ * 132 + c16_ * 8); \
        const __half* src_ = h0g + ((size_t)(b0 + row_) * Tc + (T)) * 64 + c16_ * 4; \
        asm volatile("cp.async.ca.shared.global [%0], [%1], 4;"                \
                     :: "r"(dst_), "l"(src_) : "memory");                      \
        asm volatile("cp.async.ca.shared.global [%0], [%1], 4;"                \
                     :: "r"(dst_ + 4), "l"(src_ + 2) : "memory");              \
        asm volatile("cp.async.commit_group;" ::: "memory");                   \
    }
#define WCHUNK4(c)                                                             \
    {                                                                          \
        const u32* t0 = (const u32*)(sm + H0T_OFF + (t & 1) * 4224);           \
        const uint2* bb = (const uint2*)(sm + WIH_OFF) + ((c) * 16 + w) * 64;  \
        uint2 b0t = bb[lane], b1t = bb[32 + lane];                             \
        _Pragma("unroll")                                                      \
        for (int mt = 0; mt < 2; mt++) {                                       \
            int r_ = mt * 16 + gid;                                            \
            u32 a0 = t0[r_ * 33 + 8 * (c) + tg];                               \
            u32 a1 = t0[(r_ + 8) * 33 + 8 * (c) + tg];                         \
            u32 a2 = t0[r_ * 33 + 8 * (c) + 4 + tg];                           \
            u32 a3 = t0[(r_ + 8) * 33 + 8 * (c) + 4 + tg];                     \
            mma_f16(acc[mt][0], a0, a1, a2, a3, b0t.x, b0t.y);                 \
            mma_f16(acc[mt][1], a0, a1, a2, a3, b1t.x, b1t.y);                 \
        }                                                                      \
    }

    LOAD_FRAGS(WHH_OFF, wh, 16);
    LOAD_FRAGS(WIH_OFF, wpf, 4);
    asm volatile("cp.async.commit_group;" ::: "memory");
    ISSUE_H0(0);
    for (int i = tid; i < 2 * H4_BYTES / 4; i += 512) ((u32*)sm)[i] = 0;
    CP_WAIT0();
    CL_ARRIVE();

    float4 acc[2][2];
    float cst[4] = {0.f, 0.f, 0.f, 0.f};
    float hv[4];
    const int k2 = (int)rank * 32 + w * 2 + (tg >> 1);
    const int lr[4] = {gid, gid + 8, 16 + gid, 24 + gid};
    const int cbase = (int)rank * 256 + w * 16;
    const float2 bIF = *(const float2*)&bp[cbase + 2 * tg];
    const float2 bGO = *(const float2*)&bp[cbase + 8 + 2 * tg];
    int cur = 0;

#pragma unroll 1
    for (int t = 0; t < Tc; t++) {
        const u32* hc = (const u32*)(sm + cur * H4_BYTES);
#pragma unroll
        for (int mt = 0; mt < 2; mt++) {
            acc[mt][0] = make_float4(0.f, 0.f, 0.f, 0.f);
            acc[mt][1] = make_float4(0.f, 0.f, 0.f, 0.f);
        }

        CL_WAIT();
        CP_WAIT0();          // h0 tile t landed
        ISSUE_H0(t + 1);     // prefetch next (drained at next step's CP_WAIT0)

        WCHUNK4(0); WCHUNK4(1); WCHUNK4(2); WCHUNK4(3);
#pragma unroll
        for (int c = 0; c < 16; c++) CHUNK4(c);

        ENC4_EPI(bIF, bIF, bGO, bGO, 0)
        ENC4_EPI(bIF, bIF, bGO, bGO, 1)
        ENC4_STORE_H()
        CL_ARRIVE();

        if ((tg & 1) == 0) {
#pragma unroll
            for (int r = 0; r < 4; r++)
                h_all[((size_t)(b0 + lr[r]) * Tc + t) * (Hc / 2) + k2] = pu[r];
        }
        cur ^= 1;
    }
    CL_WAIT();
}

// ---------------- decoder LSTM (H=64) ----------------
__global__ void __launch_bounds__(256) lstm_dec(
    const float4* __restrict__ w4, const void* __restrict__ xg,
    __half* __restrict__ h_out, int per_t) {
    extern __shared__ __align__(16) char smraw[];
    float2 (*shh)[Mc][4] = (float2(*)[Mc][4])smraw;
    float4* wc = (float4*)(smraw + 2 * Mc * 4 * sizeof(float2));

    const int b0 = blockIdx.x * 8;
    const int j = threadIdx.x & 63;
    const int rg = threadIdx.x >> 6;

    for (int idx = threadIdx.x; idx < Mc * Mc; idx += 256)
        wc[idx] = w4[idx];
    shh[0][j][rg] = make_float2(0.f, 0.f);
    __syncthreads();

    float c0 = 0.f, c1 = 0.f;
    ull base[4];
    if (!per_t) {
        const float* xf = (const float*)xg;
#pragma unroll
        for (int g = 0; g < 4; g++)
            base[g] = pack2f(xf[(size_t)(b0 + rg) * GMc + g * Mc + j],
                             xf[(size_t)(b0 + rg + 4) * GMc + g * Mc + j]);
    }

    int cur = 0;
#pragma unroll 1
    for (int t = 0; t < Tc; t++) {
        ull acc[4];
        if (per_t) {
            const __half* xh = (const __half*)xg;
#pragma unroll
            for (int g = 0; g < 4; g++)
                acc[g] = pack2f(
                    __half2float(xh[((size_t)(b0 + rg) * Tc + t) * GMc + g * Mc + j]),
                    __half2float(xh[((size_t)(b0 + rg + 4) * Tc + t) * GMc + g * Mc + j]));
        } else {
#pragma unroll
            for (int g = 0; g < 4; g++) acc[g] = base[g];
        }

        const float2(*shc)[4] = shh[cur];
#pragma unroll 1
        for (int k = 0; k < Mc; k += 16) {
#pragma unroll
            for (int u = 0; u < 16; u++) {
                float4 wv = wc[(k + u) * Mc + j];
                ull h2 = *(const ull*)&shc[k + u][rg];
                acc[0] = fma2f(h2, pack2f(wv.x, wv.x), acc[0]);
                acc[1] = fma2f(h2, pack2f(wv.y, wv.y), acc[1]);
                acc[2] = fma2f(h2, pack2f(wv.z, wv.z), acc[2]);
                acc[3] = fma2f(h2, pack2f(wv.w, wv.w), acc[3]);
            }
        }

        float2 iv = unpack2f(acc[0]);
        float2 fv = unpack2f(acc[1]);
        float2 gv = unpack2f(acc[2]);
        float2 ov = unpack2f(acc[3]);
        c0 = sigt(fv.x) * c0 + sigt(iv.x) * tanha(gv.x);
        float h0 = sigt(ov.x) * tanha(c0);
        c1 = sigt(fv.y) * c1 + sigt(iv.y) * tanha(gv.y);
        float h1 = sigt(ov.y) * tanha(c1);

        int nxt = cur ^ 1;
        shh[nxt][j][rg] = make_float2(h0, h1);
        h_out[((size_t)(b0 + rg) * Tc + t) * Mc + j]     = __float2half(h0);
        h_out[((size_t)(b0 + rg + 4) * Tc + t) * Mc + j] = __float2half(h1);
        __syncthreads();
        cur = nxt;
    }
}

// ---------------- launch ----------------
extern "C" void kernel_launch(void* const* d_in, const int* in_sizes, int n_in,
                              void* d_out, int out_size) {
    const float* x    = (const float*)d_in[0];
    const float* in_W = (const float*)d_in[1];
    const float* in_b = (const float*)d_in[2];
    const float* eW0i = (const float*)d_in[3];
    const float* eW0h = (const float*)d_in[4];
    const float* eb0i = (const float*)d_in[5];
    const float* eb0h = (const float*)d_in[6];
    const float* eW1i = (const float*)d_in[7];
    const float* eW1h = (const float*)d_in[8];
    const float* eb1i = (const float*)d_in[9];
    const float* eb1h = (const float*)d_in[10];
    const float* dW0i = (const float*)d_in[11];
    const float* dW0h = (const float*)d_in[12];
    const float* db0i = (const float*)d_in[13];
    const float* db0h = (const float*)d_in[14];
    const float* dW1i = (const float*)d_in[15];
    const float* dW1h = (const float*)d_in[16];
    const float* db1i = (const float*)d_in[17];
    const float* db1h = (const float*)d_in[18];
    const float* outW = (const float*)d_in[19];
    const float* outb = (const float*)d_in[20];
    float* out = (float*)d_out;

    float *xg, *mid, *bufA, *bufB, *z, *xgd0, *bp0, *bp1, *w4d0, *w4d1;
    uint2 *wh0, *wh1, *wpf0;
    __half *wp1h, *wih, *wd0h, *wd1h, *woh;
    cudaGetSymbolAddress((void**)&xg,   g_xg);
    cudaGetSymbolAddress((void**)&mid,  g_mid);
    cudaGetSymbolAddress((void**)&bufA, g_bufA);
    cudaGetSymbolAddress((void**)&bufB, g_bufB);
    cudaGetSymbolAddress((void**)&z,    g_z);
    cudaGetSymbolAddress((void**)&xgd0, g_xgd0);
    cudaGetSymbolAddress((void**)&wh0,  g_wh0);
    cudaGetSymbolAddress((void**)&wh1,  g_wh1);
    cudaGetSymbolAddress((void**)&wpf0, g_wpf0);
    cudaGetSymbolAddress((void**)&bp0,  g_bp0);
    cudaGetSymbolAddress((void**)&wp1h, g_wp1h);
    cudaGetSymbolAddress((void**)&bp1,  g_bp1);
    cudaGetSymbolAddress((void**)&wih,  g_wih);
    cudaGetSymbolAddress((void**)&wd0h, g_wd0h);
    cudaGetSymbolAddress((void**)&wd1h, g_wd1h);
    cudaGetSymbolAddress((void**)&woh,  g_woh);
    cudaGetSymbolAddress((void**)&w4d0, g_w4d0);
    cudaGetSymbolAddress((void**)&w4d1, g_w4d1);

    const int MT = Bc * Tc;
    const int DEC_SMEM = 2 * Mc * 4 * sizeof(float2) + Mc * Mc * sizeof(float4);
    static int configured = 0;
    if (!configured) {
        cudaFuncSetAttribute(lstm_enc4, cudaFuncAttributeMaxDynamicSharedMemorySize, ENC4_SMEM);
        cudaFuncSetAttribute(lstm_enc0f, cudaFuncAttributeMaxDynamicSharedMemorySize, ENC0_SMEM);
        cudaFuncSetAttribute(lstm_dec, cudaFuncAttributeMaxDynamicSharedMemorySize, DEC_SMEM);
        configured = 1;
    }

    // preps
    prep_enc0<<<321, 256>>>(eW0h, eW0i, eb0i, eb0h, wh0, wpf0, bp0);
    prep_enc1<<<1280, 256>>>(eW1h, eW1i, eb1i, eb1h, wh1, wp1h, bp1);
    prep_misc<<<512, 256>>>(in_W, dW0i, dW1i, outW, wih, wd0h, wd1h, woh);
    prep_w4<<<dim3(2, 2, 4), dim3(32, 8)>>>(dW0h, w4d0, Mc);
    prep_w4<<<dim3(2, 2, 4), dim3(32, 8)>>>(dW1h, w4d1, Mc);
    cvt16v<<<(MT * Dc / 4 + 255) / 256, 256>>>((const float4*)x, (uint2*)bufB, MT * Dc / 4);

    // 1) h0 = relu(x_h @ in_W^T + in_b) -> fp16
    gemm_h<false, true, true, true><<<dim3(MT / 128, 1), 256>>>(
        (const __half*)bufB, wih, in_b, nullptr, bufA, MT, Mc, Dc);
    // 2) enc0 FUSED (cluster-4) -> h_enc0 (fp16)
    lstm_enc0f<<<128, 512, ENC0_SMEM>>>(wh0, wpf0, (const __half*)bufA, bp0, (u32*)mid);
    // 3) xg1 (permuted, fp16) = h_enc0 @ wp1^T + bp1
    gemm_h<false, true, false, false><<<dim3(MT / 128, Gc / 128), 256>>>(
        (const __half*)mid, wp1h, bp1, nullptr, xg, MT, Gc, Hc);
    // 4) enc1 (cluster-4) -> z (fp16)
    lstm_enc4<<<128, 512, ENC4_SMEM>>>(wh1, (const __half*)xg, (u32*)z);
    // 5) xg_dec0 = z @ dW0i^T + biases (fp32 out, t-const)
    gemm_h<true, false, false, false><<<dim3(Bc / 128, GMc / 128), 256>>>(
        (const __half*)z, wd0h, db0i, db0h, xgd0, Bc, GMc, Hc);
    // 6) dec0 -> d0 (fp16)
    lstm_dec<<<Bc / 8, 256, DEC_SMEM>>>((const float4*)w4d0, xgd0, (__half*)bufA, 0);
    // 7) xg_dec1 (fp16 out)
    gemm_h<true, true, false, false><<<dim3(MT / 128, GMc / 128), 256>>>(
        (const __half*)bufA, wd1h, db1i, db1h, mid, MT, GMc, Mc);
    // 8) dec1 -> d1 (fp16)
    lstm_dec<<<Bc / 8, 256, DEC_SMEM>>>((const float4*)w4d1, mid, (__half*)bufB, 1);
    // 9) out = d1 @ out_W^T + out_b (fp32)
    gemm_h<false, false, false, false><<<dim3(MT / 128, Dc / 128), 256>>>(
        (const __half*)bufB, woh, outb, nullptr, out, MT, Dc, Mc);
}

// round 16
// speedup vs baseline: 1.0428x; 1.0428x over previous
#include <cuda_runtime.h>
#include <cuda_fp16.h>

// ---------------- problem dims ----------------
#define Bc   1024
#define Tc   100
#define Dc   256
#define Hc   256
#define Gc   1024
#define Mc   64
#define GMc  256

typedef unsigned long long ull;
typedef unsigned int u32;

// ---------------- device scratch ----------------
__device__ float g_xg  [(size_t)Bc * Tc * Gc / 2];  // fp16 xg (enc1 only)
__device__ float g_mid [(size_t)Bc * Tc * Hc];      // fp16 h_enc0 / fp16 xg_dec1
__device__ float g_bufA[(size_t)Bc * Tc * Mc];      // fp16 h0 / d0
__device__ float g_bufB[(size_t)Bc * Tc * Mc * 2];  // fp16 x_h, later fp16 d1
__device__ float g_z   [Bc * Hc];                   // fp16 z
__device__ float g_xgd0[Bc * GMc];                  // fp32
__device__ uint4 g_wh0 [32768];                     // enc0 Whh fp16 B-fragments
__device__ uint4 g_wh1 [32768];
__device__ uint2 g_wpf0[16384];                     // enc0 Wih fp16 B-fragments (K=64)
__device__ float  g_bp0 [Gc];
__device__ __half g_wp1h[Gc * Hc];
__device__ float  g_bp1 [Gc];
__device__ __half g_wih [128 * Dc];
__device__ __half g_wd0h[GMc * Hc];
__device__ __half g_wd1h[GMc * Mc];
__device__ __half g_woh [Dc * Mc];
__device__ float g_w4d0[(Mc * Mc + 1024) * 4];
__device__ float g_w4d1[(Mc * Mc + 1024) * 4];

// ---------------- helpers ----------------
__device__ __forceinline__ ull pack2f(float x, float y) {
    ull r; asm("mov.b64 %0, {%1, %2};" : "=l"(r) : "f"(x), "f"(y)); return r;
}
__device__ __forceinline__ float2 unpack2f(ull v) {
    float2 r; asm("mov.b64 {%0, %1}, %2;" : "=f"(r.x), "=f"(r.y) : "l"(v)); return r;
}
__device__ __forceinline__ ull fma2f(ull a, ull b, ull c) {
    ull d; asm("fma.rn.f32x2 %0, %1, %2, %3;" : "=l"(d) : "l"(a), "l"(b), "l"(c)); return d;
}
__device__ __forceinline__ float tanha(float x) {
    float r; asm("tanh.approx.f32 %0, %1;" : "=f"(r) : "f"(x)); return r;
}
__device__ __forceinline__ float sigt(float x) {
    return fmaf(tanha(0.5f * x), 0.5f, 0.5f);
}
__device__ __forceinline__ void mma_f16(float4& d, u32 a0, u32 a1, u32 a2, u32 a3,
                                        u32 b0, u32 b1) {
    asm("mma.sync.aligned.m16n8k16.row.col.f32.f16.f16.f32 "
        "{%0,%1,%2,%3}, {%4,%5,%6,%7}, {%8,%9}, {%0,%1,%2,%3};"
        : "+f"(d.x), "+f"(d.y), "+f"(d.z), "+f"(d.w)
        : "r"(a0), "r"(a1), "r"(a2), "r"(a3), "r"(b0), "r"(b1));
}
__device__ __forceinline__ u32 packh2(float a, float b) {
    __half2 h = __floats2half2_rn(a, b);
    return *(u32*)&h;
}
__device__ __forceinline__ float2 unpackh2(u32 v) {
    return __half22float2(*(__half2*)&v);
}
__device__ __forceinline__ uint4 ldsm4(u32 addr) {
    uint4 r;
    asm volatile("ldmatrix.sync.aligned.m8n8.x4.shared.b16 {%0,%1,%2,%3}, [%4];"
                 : "=r"(r.x), "=r"(r.y), "=r"(r.z), "=r"(r.w) : "r"(addr));
    return r;
}

// ---------------- enc0 prep: Whh frags + Wih frags (K=64) + bias ----------------
// gate-col permutation (cluster-2, 16 warps): n' = rank*512 + w*32 + nt*8 + c
//   orig = nt*256 + rank*128 + w*8 + c
__global__ void prep_enc0(const float* __restrict__ Wh, const float* __restrict__ Wi,
                          const float* __restrict__ bi, const float* __restrict__ bh,
                          uint2* __restrict__ wh, uint2* __restrict__ wpf,
                          float* __restrict__ bp) {
    int bx = blockIdx.x;
    if (bx < 256) {
        // wf[t2], t2 = (((c*2+rank)*16 + w)*4 + nt)*32 + lane
        int t2 = bx * 256 + threadIdx.x;
        int lane = t2 & 31, nt = (t2 >> 5) & 3, w = (t2 >> 7) & 15;
        int rank = (t2 >> 11) & 1, c = t2 >> 12;
        int gid = lane >> 2, tt = lane & 3;
        int n = nt * 256 + rank * 128 + w * 8 + gid;
        int k0 = 16 * c + 2 * tt;
        uint2 v;
        v.x = packh2(Wh[(size_t)n * Hc + k0],     Wh[(size_t)n * Hc + k0 + 1]);
        v.y = packh2(Wh[(size_t)n * Hc + k0 + 8], Wh[(size_t)n * Hc + k0 + 9]);
        wh[t2] = v;
    } else if (bx < 320) {
        int t2 = (bx - 256) * 256 + threadIdx.x;   // c in 0..3
        int lane = t2 & 31, nt = (t2 >> 5) & 3, w = (t2 >> 7) & 15;
        int rank = (t2 >> 11) & 1, c = t2 >> 12;
        int gid = lane >> 2, tt = lane & 3;
        int n = nt * 256 + rank * 128 + w * 8 + gid;
        int k0 = 16 * c + 2 * tt;
        uint2 v;
        v.x = packh2(Wi[(size_t)n * 64 + k0],     Wi[(size_t)n * 64 + k0 + 1]);
        v.y = packh2(Wi[(size_t)n * 64 + k0 + 8], Wi[(size_t)n * 64 + k0 + 9]);
        wpf[t2] = v;
    } else {
        for (int i = threadIdx.x; i < Gc; i += 256) {
            int rank = i >> 9, w = (i >> 5) & 15, nt = (i >> 3) & 3, c = i & 7;
            int orig = nt * 256 + rank * 128 + w * 8 + c;
            bp[i] = bi[orig] + bh[orig];
        }
    }
}

// ---------------- enc1 prep ----------------
__global__ void prep_enc16(const float* __restrict__ Wh, const float* __restrict__ Wi,
                           const float* __restrict__ bi, const float* __restrict__ bh,
                           uint2* __restrict__ wh, __half* __restrict__ Wp,
                           float* __restrict__ bp, int K) {
    int bx = blockIdx.x;
    if (bx < 256) {
        int t2 = bx * 256 + threadIdx.x;
        int lane = t2 & 31, nt = (t2 >> 5) & 3, w = (t2 >> 7) & 15;
        int rank = (t2 >> 11) & 1, c = t2 >> 12;
        int gid = lane >> 2, tt = lane & 3;
        int n = nt * 256 + rank * 128 + w * 8 + gid;
        int k0 = 16 * c + 2 * tt;
        uint2 v;
        v.x = packh2(Wh[(size_t)n * Hc + k0],     Wh[(size_t)n * Hc + k0 + 1]);
        v.y = packh2(Wh[(size_t)n * Hc + k0 + 8], Wh[(size_t)n * Hc + k0 + 9]);
        wh[t2] = v;
    } else {
        int np = bx - 256;
        int rank = np >> 9, w = (np >> 5) & 15, nt = (np >> 3) & 3, c = np & 7;
        int orig = nt * 256 + rank * 128 + w * 8 + c;
        for (int k = threadIdx.x; k < K; k += blockDim.x)
            Wp[(size_t)np * K + k] = __float2half(Wi[(size_t)orig * K + k]);
        if (threadIdx.x == 0) bp[np] = bi[orig] + bh[orig];
    }
}

// ---------------- merged misc converts: wih / wd0h / wd1h / woh ----------------
__global__ void prep_misc(const float* __restrict__ Wi, const float* __restrict__ d0,
                          const float* __restrict__ d1, const float* __restrict__ ow,
                          __half* __restrict__ wih, __half* __restrict__ wd0h,
                          __half* __restrict__ wd1h, __half* __restrict__ woh) {
    int bx = blockIdx.x;
    if (bx < 128) {
        int i = bx * 256 + threadIdx.x;                  // 32768
        wih[i] = ((i >> 8) < 64) ? __float2half(Wi[i]) : __half(0.f);
    } else if (bx < 384) {
        int i = (bx - 128) * 256 + threadIdx.x;          // 65536
        wd0h[i] = __float2half(d0[i]);
    } else if (bx < 448) {
        int i = (bx - 384) * 256 + threadIdx.x;          // 16384
        wd1h[i] = __float2half(d1[i]);
    } else {
        int i = (bx - 448) * 256 + threadIdx.x;          // 16384
        woh[i] = __float2half(ow[i]);
    }
}

__global__ void cvt16v(const float4* __restrict__ src, uint2* __restrict__ dst, int n4) {
    int i = blockIdx.x * 256 + threadIdx.x;
    if (i < n4) {
        float4 v = src[i];
        dst[i] = make_uint2(packh2(v.x, v.y), packh2(v.z, v.w));
    }
}

// ---------------- dec weight prep (both layers in one launch via blockIdx.z) -------
__global__ void prep_w4x2(const float* __restrict__ src0, const float* __restrict__ src1,
                          float* __restrict__ dst0, float* __restrict__ dst1) {
    __shared__ float tile[32][33];
    int zi = blockIdx.z;
    int g = zi & 3;
    const float* src = (zi < 4) ? src0 : src1;
    float* dst = (zi < 4) ? dst0 : dst1;
    int k0 = blockIdx.x * 32, j0 = blockIdx.y * 32;
    int x = threadIdx.x, y = threadIdx.y;
#pragma unroll
    for (int i = 0; i < 32; i += 8)
        tile[y + i][x] = src[(size_t)(g * Mc + j0 + y + i) * Mc + k0 + x];
    __syncthreads();
#pragma unroll
    for (int i = 0; i < 32; i += 8)
        dst[((size_t)(k0 + y + i) * Mc + (j0 + x)) * 4 + g] = tile[x][y + i];
}

// ---------------- fp16 GEMM: cp.async(3-stage) + ldmatrix + m16n8k16 ----------------
template <bool HASB2, bool HOUT, bool RELU, bool NGUARD>
__global__ void __launch_bounds__(256, 2) gemm_h(
    const __half* __restrict__ A, const __half* __restrict__ W,
    const float* __restrict__ b1, const float* __restrict__ b2,
    void* __restrict__ Cv, int Mdim, int Ndim, int Kdim) {
    __shared__ __align__(16) char smtile[3][16384];

    const int tid = threadIdx.x, lane = tid & 31, wid = tid >> 5;
    const int wm = wid & 3, wn = wid >> 2;
    const int gid = lane >> 2, tig = lane & 3;
    const size_t bm = (size_t)blockIdx.x * 128;
    const size_t bn = (size_t)blockIdx.y * 128;

    u32 smb;
    asm("{ .reg .u64 t; cvta.to.shared.u64 t, %1; cvt.u32.u64 %0, t; }"
        : "=r"(smb) : "l"((void*)smtile));

    u32 dA[2], dB[2];
    const __half* sA[2];
    const __half* sB[2];
#pragma unroll
    for (int i = 0; i < 2; i++) {
        int fidx = tid * 2 + i;
        int row = fidx >> 2, kc = fidx & 3;
        u32 off = (u32)(row * 64 + ((kc ^ (row & 3)) << 4));
        dA[i] = smb + off;
        sA[i] = A + (bm + row) * (size_t)Kdim + kc * 8;
        dB[i] = smb + 8192 + off;
        sB[i] = W + (bn + row) * (size_t)Kdim + kc * 8;
    }

    u32 oA[2][2], oB[2][4];
#pragma unroll
    for (int mt = 0; mt < 2; mt++) {
        int rA = wm * 32 + mt * 16 + (lane & 7) + ((lane >> 3) & 1) * 8;
#pragma unroll
        for (int s = 0; s < 2; s++) {
            int ch = s * 2 + (lane >> 4);
            oA[s][mt] = smb + rA * 64 + ((ch ^ (rA & 3)) << 4);
        }
    }
#pragma unroll
    for (int np = 0; np < 4; np++) {
        int rB = wn * 64 + np * 16 + (lane & 7) + ((lane >> 4) & 1) * 8;
#pragma unroll
        for (int s = 0; s < 2; s++) {
            int ch = s * 2 + ((lane >> 3) & 1);
            oB[s][np] = smb + 8192 + rB * 64 + ((ch ^ (rB & 3)) << 4);
        }
    }

    float4 acc[2][8];
#pragma unroll
    for (int mt = 0; mt < 2; mt++)
#pragma unroll
        for (int nt = 0; nt < 8; nt++) acc[mt][nt] = make_float4(0.f, 0.f, 0.f, 0.f);

#define GH_FILL(BUF, K0)                                                       \
    _Pragma("unroll")                                                          \
    for (int i_ = 0; i_ < 2; i_++) {                                           \
        asm volatile("cp.async.cg.shared.global [%0], [%1], 16;"               \
                     :: "r"(dA[i_] + (BUF) * 16384u), "l"(sA[i_] + (K0)) : "memory"); \
        asm volatile("cp.async.cg.shared.global [%0], [%1], 16;"               \
                     :: "r"(dB[i_] + (BUF) * 16384u), "l"(sB[i_] + (K0)) : "memory"); \
    }                                                                          \
    asm volatile("cp.async.commit_group;" ::: "memory");

#define GH_COMP(BUF)                                                           \
    _Pragma("unroll")                                                          \
    for (int s_ = 0; s_ < 2; s_++) {                                           \
        uint4 af0 = ldsm4(oA[s_][0] + (BUF) * 16384u);                         \
        uint4 af1 = ldsm4(oA[s_][1] + (BUF) * 16384u);                         \
        _Pragma("unroll")                                                      \
        for (int np_ = 0; np_ < 4; np_++) {                                    \
            uint4 bf = ldsm4(oB[s_][np_] + (BUF) * 16384u);                    \
            mma_f16(acc[0][2 * np_],     af0.x, af0.y, af0.z, af0.w, bf.x, bf.y); \
            mma_f16(acc[0][2 * np_ + 1], af0.x, af0.y, af0.z, af0.w, bf.z, bf.w); \
            mma_f16(acc[1][2 * np_],     af1.x, af1.y, af1.z, af1.w, bf.x, bf.y); \
            mma_f16(acc[1][2 * np_ + 1], af1.x, af1.y, af1.z, af1.w, bf.z, bf.w); \
        }                                                                      \
    }

    const int nb = Kdim >> 5;
    GH_FILL(0, 0);
    GH_FILL(1, 32);
#pragma unroll 1
    for (int it = 0; it < nb - 1; it++) {
        asm volatile("cp.async.wait_group 1;" ::: "memory");
        __syncthreads();
        if (it + 2 < nb) { int b2_ = (it + 2) % 3; GH_FILL(b2_, (it + 2) * 32); }
        GH_COMP(it % 3);
        __syncthreads();
    }
    asm volatile("cp.async.wait_group 0;" ::: "memory");
    __syncthreads();
    GH_COMP((nb - 1) % 3);

#pragma unroll
    for (int mt = 0; mt < 2; mt++) {
        int row0 = (int)bm + wm * 32 + mt * 16 + gid;
#pragma unroll
        for (int nt = 0; nt < 8; nt++) {
            int col = (int)bn + wn * 64 + nt * 8 + 2 * tig;
            if (NGUARD && col >= Ndim) continue;
            float bb0 = b1[col], bb1 = b1[col + 1];
            if (HASB2) { bb0 += b2[col]; bb1 += b2[col + 1]; }
            float v0 = acc[mt][nt].x + bb0, v1 = acc[mt][nt].y + bb1;
            float v2 = acc[mt][nt].z + bb0, v3 = acc[mt][nt].w + bb1;
            if (RELU) {
                v0 = fmaxf(v0, 0.f); v1 = fmaxf(v1, 0.f);
                v2 = fmaxf(v2, 0.f); v3 = fmaxf(v3, 0.f);
            }
            if (HOUT) {
                u32* Ch = (u32*)Cv;
                Ch[((size_t)row0 * Ndim + col) >> 1]       = packh2(v0, v1);
                Ch[((size_t)(row0 + 8) * Ndim + col) >> 1] = packh2(v2, v3);
            } else {
                float* C = (float*)Cv;
                *(float2*)&C[(size_t)row0 * Ndim + col]       = make_float2(v0, v1);
                *(float2*)&C[(size_t)(row0 + 8) * Ndim + col] = make_float2(v2, v3);
            }
        }
    }
}

// ================= shared enc macros (cluster-2, R13) =================
#define HS_BYTES 12288
#define CP_WAIT(n) asm volatile("cp.async.wait_group " #n ";" ::: "memory")
#define CL_ARRIVE() asm volatile("barrier.cluster.arrive.aligned;" ::: "memory")
#define CL_WAIT()   asm volatile("barrier.cluster.wait.aligned;" ::: "memory")

#define ENC_COMMON_PRELUDE                                                     \
    extern __shared__ __align__(16) char sm[];                                 \
    const int tid = threadIdx.x, lane = tid & 31, w = tid >> 5;                \
    const int gid = lane >> 2, tg = lane & 3;                                  \
    u32 rank;                                                                  \
    asm("mov.u32 %0, %%cluster_ctarank;" : "=r"(rank));                        \
    const int b0 = (blockIdx.x >> 1) * 16;                                     \
    u32 smb;                                                                   \
    asm("{ .reg .u64 t; cvta.to.shared.u64 t, %1; cvt.u32.u64 %0, t; }"        \
        : "=r"(smb) : "l"((void*)sm));

#define ISSUE_TO(c, byteoff)                                                     \
    {                                                                            \
        u32 dst_ = smb + (byteoff) + w * 1024 + lane * 16;                       \
        const uint2* src_ = wh + ((c) * 2 + (int)rank) * 2048 + w * 128 + lane * 2; \
        asm volatile("cp.async.cg.shared.global [%0], [%1], 16;"                 \
                     :: "r"(dst_), "l"(src_) : "memory");                        \
        asm volatile("cp.async.cg.shared.global [%0], [%1], 16;"                 \
                     :: "r"(dst_ + 512), "l"(src_ + 64) : "memory");             \
        asm volatile("cp.async.commit_group;" ::: "memory");                     \
    }

#define CHUNK(c, byteoff)                                                        \
    {                                                                            \
        const u32* hp_ = hc + (c) * 192;                                         \
        u32 a0_ = hp_[tg * 24 + gid];                                            \
        u32 a1_ = hp_[tg * 24 + gid + 8];                                        \
        u32 a2_ = hp_[(4 + tg) * 24 + gid];                                      \
        u32 a3_ = hp_[(4 + tg) * 24 + gid + 8];                                  \
        const uint2* bp_ = (const uint2*)(sm + (byteoff)) + w * 128 + lane;      \
        _Pragma("unroll")                                                        \
        for (int nt_ = 0; nt_ < 4; nt_++) {                                      \
            uint2 b_ = bp_[nt_ * 32];                                            \
            mma_f16(acc[nt_], a0_, a1_, a2_, a3_, b_.x, b_.y);                   \
        }                                                                        \
    }

#define ENC_EPI(XI0, XI1, XF0, XF1, XG0, XG1, XO0, XO1)                          \
    u32 p01, p23;                                                                \
    {                                                                            \
        float4 I = acc[0], F = acc[1], G = acc[2], O = acc[3];                   \
        I.x += (XI0).x; I.y += (XI0).y; I.z += (XI1).x; I.w += (XI1).y;          \
        F.x += (XF0).x; F.y += (XF0).y; F.z += (XF1).x; F.w += (XF1).y;          \
        G.x += (XG0).x; G.y += (XG0).y; G.z += (XG1).x; G.w += (XG1).y;          \
        O.x += (XO0).x; O.y += (XO0).y; O.z += (XO1).x; O.w += (XO1).y;          \
        float h[4];                                                              \
        { float cc = sigt(F.x) * cst[0] + sigt(I.x) * tanha(G.x);                \
          cst[0] = cc; h[0] = sigt(O.x) * tanha(cc); }                           \
        { float cc = sigt(F.y) * cst[1] + sigt(I.y) * tanha(G.y);                \
          cst[1] = cc; h[1] = sigt(O.y) * tanha(cc); }                           \
        { float cc = sigt(F.z) * cst[2] + sigt(I.z) * tanha(G.z);                \
          cst[2] = cc; h[2] = sigt(O.z) * tanha(cc); }                           \
        { float cc = sigt(F.w) * cst[3] + sigt(I.w) * tanha(G.w);                \
          cst[3] = cc; h[3] = sigt(O.w) * tanha(cc); }                           \
        p01 = packh2(h[0], h[1]);                                                \
        p23 = packh2(h[2], h[3]);                                                \
        const u32 hn_byte = (u32)((cur ^ 1) * HS_BYTES);                         \
        hn[k2 * 24 + gid]     = p01;                                             \
        hn[k2 * 24 + gid + 8] = p23;                                             \
        u32 la = smb + hn_byte + (u32)(k2 * 24 + gid) * 4u;                      \
        u32 ra;                                                                  \
        asm("mapa.shared::cluster.u32 %0, %1, %2;" : "=r"(ra) : "r"(la), "r"(rank ^ 1u)); \
        asm volatile("st.shared::cluster.u32 [%0], %1;" :: "r"(ra), "r"(p01));   \
        asm volatile("st.shared::cluster.u32 [%0+32], %1;" :: "r"(ra), "r"(p23)); \
    }

// ---------------- enc1: non-fused ----------------
#define RES_OFF  (2 * HS_BYTES)
#define STG_OFF  (RES_OFF + 8 * 16384)
#define ENC_SMEM (STG_OFF + 4 * 16384)

__global__ void __launch_bounds__(512, 1) __cluster_dims__(2, 1, 1)
lstm_enc_f16(const uint2* __restrict__ wh, const __half* __restrict__ xgh,
             u32* __restrict__ h_all, u32* __restrict__ z_last) {
    ENC_COMMON_PRELUDE
#define ISSUE(c) ISSUE_TO(c, STG_OFF + ((c) & 3) * 16384)

#pragma unroll
    for (int c = 0; c < 8; c++) ISSUE_TO(c, RES_OFF + c * 16384);
#pragma unroll
    for (int c = 8; c < 12; c++) ISSUE(c);

    for (int i = tid; i < HS_BYTES / 4; i += 512) ((u32*)sm)[i] = 0;
    CP_WAIT(0);
    CL_ARRIVE();

    float4 acc[4];
    float cst[4] = {0.f, 0.f, 0.f, 0.f};

    const size_t ro0 = ((size_t)(b0 + gid) * Tc) * Gc;
    const size_t ro1 = ((size_t)(b0 + gid + 8) * Tc) * Gc;
    const int ncol = (int)rank * 512 + w * 32 + 2 * tg;
    const int k2 = (int)rank * 64 + w * 4 + tg;
    const int j0 = 2 * k2;
    int cur = 0;

#define CHUNK_S(c) CHUNK(c, STG_OFF + ((c) & 3) * 16384)

#pragma unroll 1
    for (int t = 0; t < Tc; t++) {
        const u32* hc = (const u32*)(sm + cur * HS_BYTES);
        u32* hn = (u32*)(sm + (cur ^ 1) * HS_BYTES);

        u32 xv0[4], xv1[4];
        const __half* xr0 = xgh + ro0 + (size_t)t * Gc + ncol;
        const __half* xr1 = xgh + ro1 + (size_t)t * Gc + ncol;
#pragma unroll
        for (int nt = 0; nt < 4; nt++) {
            xv0[nt] = *(const u32*)(xr0 + nt * 8);
            xv1[nt] = *(const u32*)(xr1 + nt * 8);
        }
#pragma unroll
        for (int nt = 0; nt < 4; nt++) acc[nt] = make_float4(0.f, 0.f, 0.f, 0.f);

        CL_WAIT();

        if ((t & 1) == 0) {
            CHUNK_S(8);  ISSUE(12);
            CHUNK_S(9);  ISSUE(13);
            CHUNK_S(10); ISSUE(14);
            CHUNK_S(11); ISSUE(15);
#pragma unroll
            for (int c = 0; c < 8; c++) CHUNK(c, RES_OFF + c * 16384);
            CP_WAIT(3); CHUNK_S(12);
            CP_WAIT(2); CHUNK_S(13);
            CP_WAIT(1); CHUNK_S(14);
            CP_WAIT(0); CHUNK_S(15);
        } else {
            CHUNK_S(15); ISSUE(11);
            CHUNK_S(14); ISSUE(10);
            CHUNK_S(13); ISSUE(9);
            CHUNK_S(12); ISSUE(8);
#pragma unroll
            for (int c = 0; c < 8; c++) CHUNK(c, RES_OFF + c * 16384);
            CP_WAIT(3); CHUNK_S(11);
            CP_WAIT(2); CHUNK_S(10);
            CP_WAIT(1); CHUNK_S(9);
            CP_WAIT(0); CHUNK_S(8);
        }

        float2 xi0 = unpackh2(xv0[0]), xi1 = unpackh2(xv1[0]);
        float2 xf0 = unpackh2(xv0[1]), xf1 = unpackh2(xv1[1]);
        float2 xg0 = unpackh2(xv0[2]), xg1 = unpackh2(xv1[2]);
        float2 xo0 = unpackh2(xv0[3]), xo1 = unpackh2(xv1[3]);
        ENC_EPI(xi0, xi1, xf0, xf1, xg0, xg1, xo0, xo1)
        CL_ARRIVE();

        if (h_all) {
            h_all[(((size_t)(b0 + gid) * Tc + t) * Hc + j0) >> 1]     = p01;
            h_all[(((size_t)(b0 + gid + 8) * Tc + t) * Hc + j0) >> 1] = p23;
        }
        if (z_last && t == Tc - 1) {
            z_last[((size_t)(b0 + gid) * Hc + j0) >> 1]     = p01;
            z_last[((size_t)(b0 + gid + 8) * Hc + j0) >> 1] = p23;
        }
        cur ^= 1;
    }
    CL_WAIT();
}

// ---------------- enc0: FUSED input projection ----------------
#define RESF_OFF (2 * HS_BYTES)
#define STGF_OFF (RESF_OFF + 4 * 16384)
#define WPF_OFF  (STGF_OFF + 4 * 16384)
#define H0T_OFF  (WPF_OFF + 4 * 16384)
#define ENC0_SMEM (H0T_OFF + 2 * 2112)

__global__ void __launch_bounds__(512, 1) __cluster_dims__(2, 1, 1)
lstm_enc0_fused(const uint2* __restrict__ wh, const uint2* __restrict__ wpf,
                const __half* __restrict__ h0g, const float* __restrict__ bp,
                u32* __restrict__ h_all) {
    ENC_COMMON_PRELUDE
#define ISSUEF(c) ISSUE_TO(c, STGF_OFF + ((c) & 3) * 16384)
#define ISSUE_WP(c)                                                              \
    {                                                                            \
        u32 dst_ = smb + WPF_OFF + (c) * 16384 + w * 1024 + lane * 16;           \
        const uint2* src_ = wpf + ((c) * 2 + (int)rank) * 2048 + w * 128 + lane * 2; \
        asm volatile("cp.async.cg.shared.global [%0], [%1], 16;"                 \
                     :: "r"(dst_), "l"(src_) : "memory");                        \
        asm volatile("cp.async.cg.shared.global [%0], [%1], 16;"                 \
                     :: "r"(dst_ + 512), "l"(src_ + 64) : "memory");             \
        asm volatile("cp.async.commit_group;" ::: "memory");                     \
    }
#define ISSUE_H0(T)                                                              \
    {                                                                            \
        int row_ = tid >> 5, col_ = tid & 31;                                    \
        u32 dst_ = smb + H0T_OFF + (((T) & 1) ? 2112u : 0u) + row_ * 132 + col_ * 4; \
        const __half* src_ = h0g + ((size_t)(b0 + row_) * Tc + (T)) * 64 + col_ * 2; \
        asm volatile("cp.async.ca.shared.global [%0], [%1], 4;"                  \
                     :: "r"(dst_), "l"(src_) : "memory");                        \
        asm volatile("cp.async.commit_group;" ::: "memory");                     \
    }
#define WPCHUNK(c)                                                               \
    {                                                                            \
        const u32* hs_ = (const u32*)(sm + H0T_OFF + ((t & 1) ? 2112 : 0));      \
        u32 a0_ = hs_[gid * 33 + 8 * (c) + tg];                                  \
        u32 a1_ = hs_[(gid + 8) * 33 + 8 * (c) + tg];                            \
        u32 a2_ = hs_[gid * 33 + 8 * (c) + tg + 4];                              \
        u32 a3_ = hs_[(gid + 8) * 33 + 8 * (c) + tg + 4];                        \
        const uint2* bp_ = (const uint2*)(sm + WPF_OFF + (c) * 16384) + w * 128 + lane; \
        _Pragma("unroll")                                                        \
        for (int nt_ = 0; nt_ < 4; nt_++) {                                      \
            uint2 b_ = bp_[nt_ * 32];                                            \
            mma_f16(acc[nt_], a0_, a1_, a2_, a3_, b_.x, b_.y);                   \
        }                                                                        \
    }

    const int cbase = (int)rank * 512 + w * 32 + 2 * tg;
    const float2 bI = *(const float2*)&bp[cbase + 0];
    const float2 bF = *(const float2*)&bp[cbase + 8];
    const float2 bG = *(const float2*)&bp[cbase + 16];
    const float2 bO = *(const float2*)&bp[cbase + 24];

#pragma unroll
    for (int c = 0; c < 4; c++) ISSUE_TO(c, RESF_OFF + c * 16384);
#pragma unroll
    for (int c = 4; c < 8; c++) ISSUEF(c);
#pragma unroll
    for (int c = 0; c < 4; c++) ISSUE_WP(c);
    ISSUE_H0(0);

    for (int i = tid; i < HS_BYTES / 4; i += 512) ((u32*)sm)[i] = 0;
    CP_WAIT(0);
    CL_ARRIVE();

    float4 acc[4];
    float cst[4] = {0.f, 0.f, 0.f, 0.f};
    const int k2 = (int)rank * 64 + w * 4 + tg;
    const int j0 = 2 * k2;
    int cur = 0;

#define CHUNKF_S(c) CHUNK(c, STGF_OFF + ((c) & 3) * 16384)

#pragma unroll 1
    for (int t = 0; t < Tc; t++) {
        const u32* hc = (const u32*)(sm + cur * HS_BYTES);
        u32* hn = (u32*)(sm + (cur ^ 1) * HS_BYTES);
#pragma unroll
        for (int nt = 0; nt < 4; nt++) acc[nt] = make_float4(0.f, 0.f, 0.f, 0.f);

        CL_WAIT();
        CP_WAIT(0);

        ISSUE_H0(t + 1);
        CHUNKF_S(4); ISSUEF(8);
        CHUNKF_S(5); ISSUEF(9);
        CHUNKF_S(6); ISSUEF(10);
        CHUNKF_S(7); ISSUEF(11);
#pragma unroll
        for (int c = 0; c < 4; c++) CHUNK(c, RESF_OFF + c * 16384);
        WPCHUNK(0); WPCHUNK(1); WPCHUNK(2); WPCHUNK(3);
        CP_WAIT(3); CHUNKF_S(8);  ISSUEF(12);
        CP_WAIT(3); CHUNKF_S(9);  ISSUEF(13);
        CP_WAIT(3); CHUNKF_S(10); ISSUEF(14);
        CP_WAIT(3); CHUNKF_S(11); ISSUEF(15);
        CP_WAIT(3); CHUNKF_S(12);
        CP_WAIT(2); CHUNKF_S(13);
        CP_WAIT(1); CHUNKF_S(14);
        CP_WAIT(0); CHUNKF_S(15);
        ISSUEF(4); ISSUEF(5); ISSUEF(6); ISSUEF(7);

        ENC_EPI(bI, bI, bF, bF, bG, bG, bO, bO)
        CL_ARRIVE();

        h_all[(((size_t)(b0 + gid) * Tc + t) * Hc + j0) >> 1]     = p01;
        h_all[(((size_t)(b0 + gid + 8) * Tc + t) * Hc + j0) >> 1] = p23;
        cur ^= 1;
    }
    CL_WAIT();
}

// ---------------- decoder LSTM (H=64) ----------------
__global__ void __launch_bounds__(256) lstm_dec(
    const float4* __restrict__ w4, const void* __restrict__ xg,
    __half* __restrict__ h_out, int per_t) {
    extern __shared__ __align__(16) char smraw[];
    float2 (*shh)[Mc][4] = (float2(*)[Mc][4])smraw;
    float4* wc = (float4*)(smraw + 2 * Mc * 4 * sizeof(float2));

    const int b0 = blockIdx.x * 8;
    const int j = threadIdx.x & 63;
    const int rg = threadIdx.x >> 6;

    for (int idx = threadIdx.x; idx < Mc * Mc; idx += 256)
        wc[idx] = w4[idx];
    shh[0][j][rg] = make_float2(0.f, 0.f);
    __syncthreads();

    float c0 = 0.f, c1 = 0.f;
    ull base[4];
    if (!per_t) {
        const float* xf = (const float*)xg;
#pragma unroll
        for (int g = 0; g < 4; g++)
            base[g] = pack2f(xf[(size_t)(b0 + rg) * GMc + g * Mc + j],
                             xf[(size_t)(b0 + rg + 4) * GMc + g * Mc + j]);
    }

    int cur = 0;
#pragma unroll 1
    for (int t = 0; t < Tc; t++) {
        ull acc[4];
        if (per_t) {
            const __half* xh = (const __half*)xg;
#pragma unroll
            for (int g = 0; g < 4; g++)
                acc[g] = pack2f(
                    __half2float(xh[((size_t)(b0 + rg) * Tc + t) * GMc + g * Mc + j]),
                    __half2float(xh[((size_t)(b0 + rg + 4) * Tc + t) * GMc + g * Mc + j]));
        } else {
#pragma unroll
            for (int g = 0; g < 4; g++) acc[g] = base[g];
        }

        const float2(*shc)[4] = shh[cur];
#pragma unroll 1
        for (int k = 0; k < Mc; k += 16) {
#pragma unroll
            for (int u = 0; u < 16; u++) {
                float4 wv = wc[(k + u) * Mc + j];
                ull h2 = *(const ull*)&shc[k + u][rg];
                acc[0] = fma2f(h2, pack2f(wv.x, wv.x), acc[0]);
                acc[1] = fma2f(h2, pack2f(wv.y, wv.y), acc[1]);
                acc[2] = fma2f(h2, pack2f(wv.z, wv.z), acc[2]);
                acc[3] = fma2f(h2, pack2f(wv.w, wv.w), acc[3]);
            }
        }

        float2 iv = unpack2f(acc[0]);
        float2 fv = unpack2f(acc[1]);
        float2 gv = unpack2f(acc[2]);
        float2 ov = unpack2f(acc[3]);
        c0 = sigt(fv.x) * c0 + sigt(iv.x) * tanha(gv.x);
        float h0 = sigt(ov.x) * tanha(c0);
        c1 = sigt(fv.y) * c1 + sigt(iv.y) * tanha(gv.y);
        float h1 = sigt(ov.y) * tanha(c1);

        int nxt = cur ^ 1;
        shh[nxt][j][rg] = make_float2(h0, h1);
        h_out[((size_t)(b0 + rg) * Tc + t) * Mc + j]     = __float2half(h0);
        h_out[((size_t)(b0 + rg + 4) * Tc + t) * Mc + j] = __float2half(h1);
        __syncthreads();
        cur = nxt;
    }
}

// ---------------- launch ----------------
extern "C" void kernel_launch(void* const* d_in, const int* in_sizes, int n_in,
                              void* d_out, int out_size) {
    const float* x    = (const float*)d_in[0];
    const float* in_W = (const float*)d_in[1];
    const float* in_b = (const float*)d_in[2];
    const float* eW0i = (const float*)d_in[3];
    const float* eW0h = (const float*)d_in[4];
    const float* eb0i = (const float*)d_in[5];
    const float* eb0h = (const float*)d_in[6];
    const float* eW1i = (const float*)d_in[7];
    const float* eW1h = (const float*)d_in[8];
    const float* eb1i = (const float*)d_in[9];
    const float* eb1h = (const float*)d_in[10];
    const float* dW0i = (const float*)d_in[11];
    const float* dW0h = (const float*)d_in[12];
    const float* db0i = (const float*)d_in[13];
    const float* db0h = (const float*)d_in[14];
    const float* dW1i = (const float*)d_in[15];
    const float* dW1h = (const float*)d_in[16];
    const float* db1i = (const float*)d_in[17];
    const float* db1h = (const float*)d_in[18];
    const float* outW = (const float*)d_in[19];
    const float* outb = (const float*)d_in[20];
    float* out = (float*)d_out;

    float *xg, *mid, *bufA, *bufB, *z, *xgd0, *bp0, *bp1, *w4d0, *w4d1;
    uint2 *wh0, *wh1, *wpf0;
    __half *wp1h, *wih, *wd0h, *wd1h, *woh;
    cudaGetSymbolAddress((void**)&xg,   g_xg);
    cudaGetSymbolAddress((void**)&mid,  g_mid);
    cudaGetSymbolAddress((void**)&bufA, g_bufA);
    cudaGetSymbolAddress((void**)&bufB, g_bufB);
    cudaGetSymbolAddress((void**)&z,    g_z);
    cudaGetSymbolAddress((void**)&xgd0, g_xgd0);
    cudaGetSymbolAddress((void**)&wh0,  g_wh0);
    cudaGetSymbolAddress((void**)&wh1,  g_wh1);
    cudaGetSymbolAddress((void**)&wpf0, g_wpf0);
    cudaGetSymbolAddress((void**)&bp0,  g_bp0);
    cudaGetSymbolAddress((void**)&wp1h, g_wp1h);
    cudaGetSymbolAddress((void**)&bp1,  g_bp1);
    cudaGetSymbolAddress((void**)&wih,  g_wih);
    cudaGetSymbolAddress((void**)&wd0h, g_wd0h);
    cudaGetSymbolAddress((void**)&wd1h, g_wd1h);
    cudaGetSymbolAddress((void**)&woh,  g_woh);
    cudaGetSymbolAddress((void**)&w4d0, g_w4d0);
    cudaGetSymbolAddress((void**)&w4d1, g_w4d1);

    const int MT = Bc * Tc;
    const int DEC_SMEM = 2 * Mc * 4 * sizeof(float2) + Mc * Mc * sizeof(float4);
    static int configured = 0;
    if (!configured) {
        cudaFuncSetAttribute(lstm_enc_f16, cudaFuncAttributeMaxDynamicSharedMemorySize, ENC_SMEM);
        cudaFuncSetAttribute(lstm_enc0_fused, cudaFuncAttributeMaxDynamicSharedMemorySize, ENC0_SMEM);
        cudaFuncSetAttribute(lstm_dec, cudaFuncAttributeMaxDynamicSharedMemorySize, DEC_SMEM);
        configured = 1;
    }

    // preps (longest first; dec preps merged into one launch)
    prep_enc16<<<1280, 256>>>(eW1h, eW1i, eb1i, eb1h, wh1, wp1h, bp1, Hc);
    prep_enc0<<<321, 256>>>(eW0h, eW0i, eb0i, eb0h, wh0, wpf0, bp0);
    prep_misc<<<512, 256>>>(in_W, dW0i, dW1i, outW, wih, wd0h, wd1h, woh);
    prep_w4x2<<<dim3(2, 2, 8), dim3(32, 8)>>>(dW0h, dW1h, w4d0, w4d1);
    cvt16v<<<(MT * Dc / 4 + 255) / 256, 256>>>((const float4*)x, (uint2*)bufB, MT * Dc / 4);

    // 1) h0 = relu(x_h @ in_W^T + in_b) -> fp16
    gemm_h<false, true, true, true><<<dim3(MT / 128, 1), 256>>>(
        (const __half*)bufB, wih, in_b, nullptr, bufA, MT, Mc, Dc);
    // 2) enc0 FUSED (input proj inside) -> h_enc0 (fp16)
    lstm_enc0_fused<<<128, 512, ENC0_SMEM>>>(wh0, wpf0, (const __half*)bufA, bp0, (u32*)mid);
    // 3) xg1 (permuted, fp16) = h_enc0 @ wp1^T + bp1
    gemm_h<false, true, false, false><<<dim3(MT / 128, Gc / 128), 256>>>(
        (const __half*)mid, wp1h, bp1, nullptr, xg, MT, Gc, Hc);
    // 4) enc1 -> z (fp16)
    lstm_enc_f16<<<128, 512, ENC_SMEM>>>(wh1, (const __half*)xg, nullptr, (u32*)z);
    // 5) xg_dec0 = z @ dW0i^T + biases (fp32 out, t-const)
    gemm_h<true, false, false, false><<<dim3(Bc / 128, GMc / 128), 256>>>(
        (const __half*)z, wd0h, db0i, db0h, xgd0, Bc, GMc, Hc);
    // 6) dec0 -> d0 (fp16)
    lstm_dec<<<Bc / 8, 256, DEC_SMEM>>>((const float4*)w4d0, xgd0, (__half*)bufA, 0);
    // 7) xg_dec1 (fp16 out)
    gemm_h<true, true, false, false><<<dim3(MT / 128, GMc / 128), 256>>>(
        (const __half*)bufA, wd1h, db1i, db1h, mid, MT, GMc, Mc);
    // 8) dec1 -> d1 (fp16)
    lstm_dec<<<Bc / 8, 256, DEC_SMEM>>>((const float4*)w4d1, mid, (__half*)bufB, 1);
    // 9) out = d1 @ out_W^T + out_b (fp32)
    gemm_h<false, false, false, false><<<dim3(MT / 128, Dc / 128), 256>>>(
        (const __half*)bufB, woh, outb, nullptr, out, MT, Dc, Mc);
}